// round 16
// baseline (speedup 1.0000x reference)
#include <cuda_runtime.h>
#include <cuda_bf16.h>
#include <cstdint>

#define MAXN   500000
#define IN     128
#define H1     32
#define H2     32
#define NOS    4
#define TR     128                   // rows per tile
#define MAXSEG 3907                  // ceil(MAXN/TR)
#define SEGA   (MAXSEG * TR)
#define PADN   (NOS * SEGA)
#define MAXCB  1954
#define GRID_MLP 304                 // persistent: 2 CTAs/SM x 152 SMs

typedef unsigned long long ull;

// ---- smem byte offsets (k_mlp) ----
#define OFF_A0    0          // buf0 bf16 [128][136] = 34816
#define OFF_A1    34816      // buf1 bf16 [128][136] = 34816
#define OFF_W0    69632      // W0T bf16 [c=32][136] = 8704
#define OFF_W1    78336      // W1T bf16 [c=32][40]  = 2560
#define OFF_B0    80896
#define OFF_B1    81024
#define OFF_W2    81152
#define OFF_B2    81280
#define OFF_SRED  81296      // 256 floats
#define SMEM_BYTES 82432

// single-MUFU tanh (sm_75+)
__device__ __forceinline__ float fast_tanh(float x) {
    float r;
    asm("tanh.approx.f32 %0, %1;" : "=f"(r) : "f"(x));
    return r;
}
__device__ __forceinline__ uint32_t packbf2(float lo, float hi) {
    __nv_bfloat162 p = __floats2bfloat162_rn(lo, hi);
    return *(uint32_t*)&p;
}
__device__ __forceinline__ void mma16(float& d0, float& d1, float& d2, float& d3,
                                      uint32_t a0, uint32_t a1, uint32_t a2, uint32_t a3,
                                      uint32_t b0, uint32_t b1) {
    asm volatile(
        "mma.sync.aligned.m16n8k16.row.col.f32.bf16.bf16.f32 "
        "{%0,%1,%2,%3}, {%4,%5,%6,%7}, {%8,%9}, {%0,%1,%2,%3};"
        : "+f"(d0), "+f"(d1), "+f"(d2), "+f"(d3)
        : "r"(a0), "r"(a1), "r"(a2), "r"(a3), "r"(b0), "r"(b1));
}
__device__ __forceinline__ void ldm4(uint32_t& r0, uint32_t& r1, uint32_t& r2, uint32_t& r3,
                                     uint32_t addr) {
    asm volatile("ldmatrix.sync.aligned.m8n8.x4.shared.b16 {%0,%1,%2,%3}, [%4];"
                 : "=r"(r0), "=r"(r1), "=r"(r2), "=r"(r3) : "r"(addr));
}
__device__ __forceinline__ uint32_t smem_u32(const void* p) {
    uint32_t a;
    asm("{ .reg .u64 t; cvta.to.shared.u64 t, %1; cvt.u32.u64 %0, t; }" : "=r"(a) : "l"(p));
    return a;
}

// ---------------- device scratch ----------------
__device__ int   g_cursor[NOS] = {0, SEGA, 2 * SEGA, 3 * SEGA};
__device__ unsigned g_done = 0u;
__device__ int   g_order[PADN];
__device__ float g_partial[GRID_MLP];

// ---------------- scatter (self-detects int64 vs int32) ----------------
__global__ void k_scatter(const void* sp, int n) {
    __shared__ int h[NOS];
    __shared__ int basebuf[NOS];
    __shared__ int bad;
    const int t = threadIdx.x;
    if (t < NOS) h[t] = 0;
    if (t == 0) bad = 0;
    __syncthreads();
    int lim = (n / 2 < 512) ? (n / 2) : 512;
    for (int i = t; i < lim; i += 256)
        if (((const ull*)sp)[i] >= 4ull) bad = 1;
    __syncthreads();
    const int is64 = !bad;
    int i = blockIdx.x * 256 + t;
    int s = 0, r = 0;
    bool valid = (i < n);
    if (valid) {
        s = is64 ? (int)((const long long*)sp)[i] : ((const int*)sp)[i];
        r = atomicAdd(&h[s], 1);
    }
    __syncthreads();
    if (t < NOS && h[t] > 0) basebuf[t] = atomicAdd(&g_cursor[t], h[t]);
    __syncthreads();
    if (valid) g_order[basebuf[s] + r] = i;
}

// ---------------- persistent double-buffered bf16 HMMA MLP --------------
// r15 body + L2 prefetch of tile j+2 (desc lines + g_order indices)
__global__ void __launch_bounds__(256, 2)
k_mlp(const float* __restrict__ desc,
      const float* __restrict__ W0, const float* __restrict__ b0,
      const float* __restrict__ W1, const float* __restrict__ b1,
      const float* __restrict__ W2, const float* __restrict__ b2,
      float* __restrict__ out)
{
    extern __shared__ char smc[];
    const int t = threadIdx.x, wid = t >> 5, lane = t & 31;
    const int gid = lane >> 2, tid = lane & 3;
    const int wb = wid * 16;

    __nv_bfloat16* sW0 = (__nv_bfloat16*)(smc + OFF_W0);
    __nv_bfloat16* sW1 = (__nv_bfloat16*)(smc + OFF_W1);
    float* vb0 = (float*)(smc + OFF_B0);
    float* vb1 = (float*)(smc + OFF_B1);
    float* vw2 = (float*)(smc + OFF_W2);
    float* vb2 = (float*)(smc + OFF_B2);
    float* sred = (float*)(smc + OFF_SRED);
    const uint32_t a0Addr = smem_u32(smc + OFF_A0);
    const uint32_t a1Addr = smem_u32(smc + OFF_A1);

    const int c0 = g_cursor[0] - 0 * SEGA;
    const int c1 = g_cursor[1] - 1 * SEGA;
    const int c2 = g_cursor[2] - 2 * SEGA;
    const int c3 = g_cursor[3] - 3 * SEGA;
    const int t0 = (c0 + TR - 1) / TR, t1 = (c1 + TR - 1) / TR;
    const int t2 = (c2 + TR - 1) / TR, t3 = (c3 + TR - 1) / TR;
    const int p1 = t0 + t1, p2 = p1 + t2, total = p2 + t3;

    const int per = (total + GRID_MLP - 1) / GRID_MLP;
    const int jb = blockIdx.x * per;
    int je = jb + per; if (je > total) je = total;

    const int lrow = ((lane >> 3) & 1) * 8 + (lane & 7);
    const int lcol = (lane >> 4) * 8;

    float esum = 0.f;

    if (jb < je) {
        auto tile_sp = [&](int j) {
            return (j < t0) ? 0 : (j < p1) ? 1 : (j < p2) ? 2 : 3;
        };
        auto tile_base = [&](int j, int sp) {
            int pre = (sp == 0) ? 0 : (sp == 1) ? t0 : (sp == 2) ? p1 : p2;
            return sp * SEGA + (j - pre) * TR;
        };
        auto tile_cnt = [&](int sp) {
            return (sp == 0) ? c0 : (sp == 1) ? c1 : (sp == 2) ? c2 : c3;
        };

        auto load_weights = [&](int sp) {
            const float4* w4 = (const float4*)(W0 + sp * IN * H1);
#pragma unroll
            for (int e = t; e < IN * H1 / 4; e += 256) {
                int k = e >> 3, c = (e & 7) * 4;
                float4 v = w4[e];
                sW0[(c + 0) * 136 + k] = __float2bfloat16_rn(v.x);
                sW0[(c + 1) * 136 + k] = __float2bfloat16_rn(v.y);
                sW0[(c + 2) * 136 + k] = __float2bfloat16_rn(v.z);
                sW0[(c + 3) * 136 + k] = __float2bfloat16_rn(v.w);
            }
            const float4* w14 = (const float4*)(W1 + sp * H1 * H2);
#pragma unroll
            for (int e = t; e < H1 * H2 / 4; e += 256) {
                int k = e >> 3, c = (e & 7) * 4;
                float4 v = w14[e];
                sW1[(c + 0) * 40 + k] = __float2bfloat16_rn(v.x);
                sW1[(c + 1) * 40 + k] = __float2bfloat16_rn(v.y);
                sW1[(c + 2) * 40 + k] = __float2bfloat16_rn(v.z);
                sW1[(c + 3) * 40 + k] = __float2bfloat16_rn(v.w);
            }
            if (t < H1) vb0[t] = b0[sp * H1 + t];
            if (t < H2) { vb1[t] = b1[sp * H2 + t]; vw2[t] = W2[sp * H2 + t]; }
            if (t == 0) vb2[0] = b2[sp];
        };

        auto load_idx = [&](int j, int sp) {
            int idx = -1;
            if (lane < 16) {
                int base = tile_base(j, sp);
                int local = base - sp * SEGA + wb + lane;
                if (local < tile_cnt(sp)) idx = g_order[base + wb + lane];
            }
            return idx;
        };

        int spc = tile_sp(jb);
        int cidx = load_idx(jb, spc);

        load_weights(spc);
#pragma unroll
        for (int b = 0; b < 2; b++) {
            float4 v[8];
#pragma unroll
            for (int j2 = 0; j2 < 8; j2++) {
                int idx = __shfl_sync(0xffffffffu, cidx, b * 8 + j2);
                v[j2] = make_float4(0.f, 0.f, 0.f, 0.f);
                if (idx >= 0)
                    v[j2] = *(const float4*)(desc + (size_t)idx * IN + lane * 4);
            }
#pragma unroll
            for (int j2 = 0; j2 < 8; j2++) {
                int row = wb + b * 8 + j2;
                uint2 u;
                u.x = packbf2(v[j2].x, v[j2].y);
                u.y = packbf2(v[j2].z, v[j2].w);
                *(uint2*)(smc + OFF_A0 + (row * 136 + lane * 4) * 2) = u;
            }
        }
        int nidx = (jb + 1 < je) ? load_idx(jb + 1, tile_sp(jb + 1)) : -1;
        __syncthreads();

        for (int j = jb; j < je; j++) {
            const uint32_t curA = ((j - jb) & 1) ? a1Addr : a0Addr;
            const char*   nxtP = smc + (((j - jb) & 1) ? OFF_A0 : OFF_A1);
            const bool hasnext = (j + 1 < je);
            const int spn = hasnext ? tile_sp(j + 1) : spc;

            // (0) prefetch tile j+2: indices (register chain) + L2 lines
            int pidx = -1;
            if (j + 2 < je) {
                pidx = load_idx(j + 2, tile_sp(j + 2));
                int prow = __shfl_sync(0xffffffffu, pidx, lane >> 1);
                if (prow >= 0) {
                    const char* pb = (const char*)(desc + (size_t)prow * IN)
                                     + (lane & 1) * 256;
                    asm volatile("prefetch.global.L2 [%0];" :: "l"(pb));
                    asm volatile("prefetch.global.L2 [%0];" :: "l"(pb + 128));
                }
            }

            // (1) issue batch0 LDGs for next tile
            float4 v0[8];
            if (hasnext) {
#pragma unroll
                for (int j2 = 0; j2 < 8; j2++) {
                    int idx = __shfl_sync(0xffffffffu, nidx, j2);
                    v0[j2] = make_float4(0.f, 0.f, 0.f, 0.f);
                    if (idx >= 0)
                        v0[j2] = *(const float4*)(desc + (size_t)idx * IN + lane * 4);
                }
            }

            // (2) layer 0 MMA on current tile
            float d[4][4];
#pragma unroll
            for (int nt = 0; nt < 4; nt++)
#pragma unroll
                for (int i = 0; i < 4; i++) d[nt][i] = 0.f;
#pragma unroll
            for (int kk = 0; kk < 8; kk++) {
                const int k0 = kk * 16;
                uint32_t a0f, a1f, a2f, a3f;
                ldm4(a0f, a1f, a2f, a3f,
                     curA + ((wb + lrow) * 136 + k0 + lcol) * 2);
#pragma unroll
                for (int nt = 0; nt < 4; nt++) {
                    const __nv_bfloat16* bb = sW0 + (nt * 8 + gid) * 136 + k0 + 2 * tid;
                    uint32_t b0f = *(const uint32_t*)bb;
                    uint32_t b1f = *(const uint32_t*)(bb + 8);
                    mma16(d[nt][0], d[nt][1], d[nt][2], d[nt][3],
                          a0f, a1f, a2f, a3f, b0f, b1f);
                }
            }

            // (3) issue batch1 LDGs for next tile BEFORE draining v0
            float4 v1[8];
            if (hasnext) {
#pragma unroll
                for (int j2 = 0; j2 < 8; j2++) {
                    int idx = __shfl_sync(0xffffffffu, nidx, 8 + j2);
                    v1[j2] = make_float4(0.f, 0.f, 0.f, 0.f);
                    if (idx >= 0)
                        v1[j2] = *(const float4*)(desc + (size_t)idx * IN + lane * 4);
                }
            }

            // (4) convert + store batch0 of next tile
            if (hasnext) {
#pragma unroll
                for (int j2 = 0; j2 < 8; j2++) {
                    int row = wb + j2;
                    uint2 u;
                    u.x = packbf2(v0[j2].x, v0[j2].y);
                    u.y = packbf2(v0[j2].z, v0[j2].w);
                    *(uint2*)(nxtP + (row * 136 + lane * 4) * 2) = u;
                }
            }

            // (5) epilogue0 + layer1 entirely in registers
            float e1[4][4];
#pragma unroll
            for (int nt = 0; nt < 4; nt++)
#pragma unroll
                for (int i = 0; i < 4; i++) e1[nt][i] = 0.f;
#pragma unroll
            for (int kk = 0; kk < 2; kk++) {
                const int cc0 = (2 * kk) * 8 + 2 * tid;
                const int cc1 = (2 * kk + 1) * 8 + 2 * tid;
                uint32_t a0f = packbf2(fast_tanh(d[2 * kk][0] + vb0[cc0]),
                                       fast_tanh(d[2 * kk][1] + vb0[cc0 + 1]));
                uint32_t a1f = packbf2(fast_tanh(d[2 * kk][2] + vb0[cc0]),
                                       fast_tanh(d[2 * kk][3] + vb0[cc0 + 1]));
                uint32_t a2f = packbf2(fast_tanh(d[2 * kk + 1][0] + vb0[cc1]),
                                       fast_tanh(d[2 * kk + 1][1] + vb0[cc1 + 1]));
                uint32_t a3f = packbf2(fast_tanh(d[2 * kk + 1][2] + vb0[cc1]),
                                       fast_tanh(d[2 * kk + 1][3] + vb0[cc1 + 1]));
                const int k0 = kk * 16;
#pragma unroll
                for (int nt = 0; nt < 4; nt++) {
                    const __nv_bfloat16* bb = sW1 + (nt * 8 + gid) * 40 + k0 + 2 * tid;
                    uint32_t b0f = *(const uint32_t*)bb;
                    uint32_t b1f = *(const uint32_t*)(bb + 8);
                    mma16(e1[nt][0], e1[nt][1], e1[nt][2], e1[nt][3],
                          a0f, a1f, a2f, a3f, b0f, b1f);
                }
            }

            // (6) epilogue 1: bias + tanh + W2 dot (energy)
            {
                float p0 = 0.f, p1e = 0.f;
#pragma unroll
                for (int nt = 0; nt < 4; nt++) {
                    int cc = nt * 8 + 2 * tid;
                    p0  += fast_tanh(e1[nt][0] + vb1[cc])     * vw2[cc];
                    p0  += fast_tanh(e1[nt][1] + vb1[cc + 1]) * vw2[cc + 1];
                    p1e += fast_tanh(e1[nt][2] + vb1[cc])     * vw2[cc];
                    p1e += fast_tanh(e1[nt][3] + vb1[cc + 1]) * vw2[cc + 1];
                }
                p0  += __shfl_xor_sync(0xffffffffu, p0, 1);
                p0  += __shfl_xor_sync(0xffffffffu, p0, 2);
                p1e += __shfl_xor_sync(0xffffffffu, p1e, 1);
                p1e += __shfl_xor_sync(0xffffffffu, p1e, 2);
                int i0 = __shfl_sync(0xffffffffu, cidx, gid);
                int i1 = __shfl_sync(0xffffffffu, cidx, gid + 8);
                if (tid == 0) {
                    float bb2 = vb2[0];
                    if (i0 >= 0) esum += p0 + bb2;
                    if (i1 >= 0) esum += p1e + bb2;
                }
            }

            // (7) convert + store batch1 of next tile
            if (hasnext) {
#pragma unroll
                for (int j2 = 0; j2 < 8; j2++) {
                    int row = wb + 8 + j2;
                    uint2 u;
                    u.x = packbf2(v1[j2].x, v1[j2].y);
                    u.y = packbf2(v1[j2].z, v1[j2].w);
                    *(uint2*)(nxtP + (row * 136 + lane * 4) * 2) = u;
                }
            }

            // (8) barrier: next buffer complete; cur free for reuse
            __syncthreads();

            // (9) species change -> reload weights (rare)
            if (hasnext && spn != spc) {
                load_weights(spn);
                __syncthreads();
            }
            spc = spn;
            cidx = nidx;
            nidx = pidx;
        }
    }

    // ---- block reduction of per-thread energy ----
    sred[t] = esum;
    __syncthreads();
    if (t < 128) sred[t] += sred[t + 128];
    __syncthreads();
    if (t < 64) sred[t] += sred[t + 64];
    __syncthreads();
    if (t < 32) {
        float v = sred[t] + sred[t + 32];
#pragma unroll
        for (int o = 16; o > 0; o >>= 1) v += __shfl_down_sync(0xffffffffu, v, o);
        if (t == 0) g_partial[blockIdx.x] = v;
    }

    // ---- last-block: final reduction + replay-state reset ----
    __shared__ int slast;
    __syncthreads();
    if (t == 0) {
        __threadfence();
        unsigned prev = atomicAdd(&g_done, 1u);
        slast = (prev + 1 == gridDim.x);
    }
    __syncthreads();
    if (slast) {
        float v = 0.f;
        for (int i = t; i < (int)gridDim.x; i += 256) v += g_partial[i];
        sred[t] = v;
        __syncthreads();
        if (t < 128) sred[t] += sred[t + 128];
        __syncthreads();
        if (t < 64) sred[t] += sred[t + 64];
        __syncthreads();
        if (t < 32) {
            float x = sred[t] + sred[t + 32];
#pragma unroll
            for (int o = 16; o > 0; o >>= 1) x += __shfl_down_sync(0xffffffffu, x, o);
            if (t == 0) out[0] = x;
        }
        if (t < NOS) g_cursor[t] = t * SEGA;
        if (t == 0) g_done = 0u;
    }
}

// ---------------- launcher: TWO kernels total ----------------
extern "C" void kernel_launch(void* const* d_in, const int* in_sizes, int n_in,
                              void* d_out, int out_size)
{
    const float* desc    = (const float*)d_in[0];
    const void*  species = d_in[1];
    const float* W0 = (const float*)d_in[2];
    const float* b0 = (const float*)d_in[3];
    const float* W1 = (const float*)d_in[4];
    const float* b1 = (const float*)d_in[5];
    const float* W2 = (const float*)d_in[6];
    const float* b2 = (const float*)d_in[7];

    int n = in_sizes[1];
    if (n > MAXN) n = MAXN;

    int nb_atoms = (n + 255) / 256;
    if (nb_atoms > MAXCB) nb_atoms = MAXCB;

    cudaFuncSetAttribute(k_mlp, cudaFuncAttributeMaxDynamicSharedMemorySize, SMEM_BYTES);

    k_scatter<<<nb_atoms, 256>>>(species, n);
    k_mlp<<<GRID_MLP, 256, SMEM_BYTES>>>(desc, W0, b0, W1, b1, W2, b2, (float*)d_out);
}

// round 17
// speedup vs baseline: 1.0714x; 1.0714x over previous
#include <cuda_runtime.h>
#include <cuda_bf16.h>
#include <cstdint>

#define MAXN   500000
#define IN     128
#define H1     32
#define H2     32
#define NOS    4
#define TR     128                   // rows per tile
#define MAXSEG 3907                  // ceil(MAXN/TR)
#define SEGA   (MAXSEG * TR)
#define PADN   (NOS * SEGA)
#define MAXCB  1954
#define GRID_MLP 304                 // persistent: 2 CTAs/SM x 152 SMs

typedef unsigned long long ull;

// ---- smem byte offsets (k_mlp) ----
#define OFF_A0    0          // buf0 bf16 [128][136] = 34816
#define OFF_A1    34816      // buf1 bf16 [128][136] = 34816
#define OFF_W0    69632      // W0T bf16 [c=32][136] = 8704
#define OFF_W1    78336      // W1T bf16 [c=32][40]  = 2560
#define OFF_B0    80896
#define OFF_B1    81024
#define OFF_W2    81152
#define OFF_B2    81280
#define OFF_SRED  81296      // 256 floats
#define SMEM_BYTES 82432

// single-MUFU tanh (sm_75+)
__device__ __forceinline__ float fast_tanh(float x) {
    float r;
    asm("tanh.approx.f32 %0, %1;" : "=f"(r) : "f"(x));
    return r;
}
__device__ __forceinline__ uint32_t packbf2(float lo, float hi) {
    __nv_bfloat162 p = __floats2bfloat162_rn(lo, hi);
    return *(uint32_t*)&p;
}
__device__ __forceinline__ void mma16(float& d0, float& d1, float& d2, float& d3,
                                      uint32_t a0, uint32_t a1, uint32_t a2, uint32_t a3,
                                      uint32_t b0, uint32_t b1) {
    asm volatile(
        "mma.sync.aligned.m16n8k16.row.col.f32.bf16.bf16.f32 "
        "{%0,%1,%2,%3}, {%4,%5,%6,%7}, {%8,%9}, {%0,%1,%2,%3};"
        : "+f"(d0), "+f"(d1), "+f"(d2), "+f"(d3)
        : "r"(a0), "r"(a1), "r"(a2), "r"(a3), "r"(b0), "r"(b1));
}
__device__ __forceinline__ void ldm4(uint32_t& r0, uint32_t& r1, uint32_t& r2, uint32_t& r3,
                                     uint32_t addr) {
    asm volatile("ldmatrix.sync.aligned.m8n8.x4.shared.b16 {%0,%1,%2,%3}, [%4];"
                 : "=r"(r0), "=r"(r1), "=r"(r2), "=r"(r3) : "r"(addr));
}
__device__ __forceinline__ uint32_t smem_u32(const void* p) {
    uint32_t a;
    asm("{ .reg .u64 t; cvta.to.shared.u64 t, %1; cvt.u32.u64 %0, t; }" : "=r"(a) : "l"(p));
    return a;
}

// ---------------- device scratch ----------------
__device__ int   g_cursor[NOS] = {0, SEGA, 2 * SEGA, 3 * SEGA};
__device__ unsigned g_done = 0u;
__device__ int   g_order[PADN];
__device__ float g_partial[GRID_MLP];

// ---------------- scatter (self-detects int64 vs int32) ----------------
__global__ void k_scatter(const void* sp, int n) {
    __shared__ int h[NOS];
    __shared__ int basebuf[NOS];
    __shared__ int bad;
    const int t = threadIdx.x;
    if (t < NOS) h[t] = 0;
    if (t == 0) bad = 0;
    __syncthreads();
    int lim = (n / 2 < 512) ? (n / 2) : 512;
    for (int i = t; i < lim; i += 256)
        if (((const ull*)sp)[i] >= 4ull) bad = 1;
    __syncthreads();
    const int is64 = !bad;
    int i = blockIdx.x * 256 + t;
    int s = 0, r = 0;
    bool valid = (i < n);
    if (valid) {
        s = is64 ? (int)((const long long*)sp)[i] : ((const int*)sp)[i];
        r = atomicAdd(&h[s], 1);
    }
    __syncthreads();
    if (t < NOS && h[t] > 0) basebuf[t] = atomicAdd(&g_cursor[t], h[t]);
    __syncthreads();
    if (valid) g_order[basebuf[s] + r] = i;
}

// ---------------- persistent double-buffered bf16 HMMA MLP --------------
// r15 body with batch0+batch1 issued together BEFORE the layer-0 MMA
__global__ void __launch_bounds__(256, 2)
k_mlp(const float* __restrict__ desc,
      const float* __restrict__ W0, const float* __restrict__ b0,
      const float* __restrict__ W1, const float* __restrict__ b1,
      const float* __restrict__ W2, const float* __restrict__ b2,
      float* __restrict__ out)
{
    extern __shared__ char smc[];
    const int t = threadIdx.x, wid = t >> 5, lane = t & 31;
    const int gid = lane >> 2, tid = lane & 3;
    const int wb = wid * 16;

    __nv_bfloat16* sW0 = (__nv_bfloat16*)(smc + OFF_W0);
    __nv_bfloat16* sW1 = (__nv_bfloat16*)(smc + OFF_W1);
    float* vb0 = (float*)(smc + OFF_B0);
    float* vb1 = (float*)(smc + OFF_B1);
    float* vw2 = (float*)(smc + OFF_W2);
    float* vb2 = (float*)(smc + OFF_B2);
    float* sred = (float*)(smc + OFF_SRED);
    const uint32_t a0Addr = smem_u32(smc + OFF_A0);
    const uint32_t a1Addr = smem_u32(smc + OFF_A1);

    const int c0 = g_cursor[0] - 0 * SEGA;
    const int c1 = g_cursor[1] - 1 * SEGA;
    const int c2 = g_cursor[2] - 2 * SEGA;
    const int c3 = g_cursor[3] - 3 * SEGA;
    const int t0 = (c0 + TR - 1) / TR, t1 = (c1 + TR - 1) / TR;
    const int t2 = (c2 + TR - 1) / TR, t3 = (c3 + TR - 1) / TR;
    const int p1 = t0 + t1, p2 = p1 + t2, total = p2 + t3;

    const int per = (total + GRID_MLP - 1) / GRID_MLP;
    const int jb = blockIdx.x * per;
    int je = jb + per; if (je > total) je = total;

    const int lrow = ((lane >> 3) & 1) * 8 + (lane & 7);
    const int lcol = (lane >> 4) * 8;

    float esum = 0.f;

    if (jb < je) {
        auto tile_sp = [&](int j) {
            return (j < t0) ? 0 : (j < p1) ? 1 : (j < p2) ? 2 : 3;
        };
        auto tile_base = [&](int j, int sp) {
            int pre = (sp == 0) ? 0 : (sp == 1) ? t0 : (sp == 2) ? p1 : p2;
            return sp * SEGA + (j - pre) * TR;
        };
        auto tile_cnt = [&](int sp) {
            return (sp == 0) ? c0 : (sp == 1) ? c1 : (sp == 2) ? c2 : c3;
        };

        auto load_weights = [&](int sp) {
            const float4* w4 = (const float4*)(W0 + sp * IN * H1);
#pragma unroll
            for (int e = t; e < IN * H1 / 4; e += 256) {
                int k = e >> 3, c = (e & 7) * 4;
                float4 v = w4[e];
                sW0[(c + 0) * 136 + k] = __float2bfloat16_rn(v.x);
                sW0[(c + 1) * 136 + k] = __float2bfloat16_rn(v.y);
                sW0[(c + 2) * 136 + k] = __float2bfloat16_rn(v.z);
                sW0[(c + 3) * 136 + k] = __float2bfloat16_rn(v.w);
            }
            const float4* w14 = (const float4*)(W1 + sp * H1 * H2);
#pragma unroll
            for (int e = t; e < H1 * H2 / 4; e += 256) {
                int k = e >> 3, c = (e & 7) * 4;
                float4 v = w14[e];
                sW1[(c + 0) * 40 + k] = __float2bfloat16_rn(v.x);
                sW1[(c + 1) * 40 + k] = __float2bfloat16_rn(v.y);
                sW1[(c + 2) * 40 + k] = __float2bfloat16_rn(v.z);
                sW1[(c + 3) * 40 + k] = __float2bfloat16_rn(v.w);
            }
            if (t < H1) vb0[t] = b0[sp * H1 + t];
            if (t < H2) { vb1[t] = b1[sp * H2 + t]; vw2[t] = W2[sp * H2 + t]; }
            if (t == 0) vb2[0] = b2[sp];
        };

        auto load_idx = [&](int j, int sp) {
            int idx = -1;
            if (lane < 16) {
                int base = tile_base(j, sp);
                int local = base - sp * SEGA + wb + lane;
                if (local < tile_cnt(sp)) idx = g_order[base + wb + lane];
            }
            return idx;
        };

        int spc = tile_sp(jb);
        int cidx = load_idx(jb, spc);

        load_weights(spc);
#pragma unroll
        for (int b = 0; b < 2; b++) {
            float4 v[8];
#pragma unroll
            for (int j2 = 0; j2 < 8; j2++) {
                int idx = __shfl_sync(0xffffffffu, cidx, b * 8 + j2);
                v[j2] = make_float4(0.f, 0.f, 0.f, 0.f);
                if (idx >= 0)
                    v[j2] = *(const float4*)(desc + (size_t)idx * IN + lane * 4);
            }
#pragma unroll
            for (int j2 = 0; j2 < 8; j2++) {
                int row = wb + b * 8 + j2;
                uint2 u;
                u.x = packbf2(v[j2].x, v[j2].y);
                u.y = packbf2(v[j2].z, v[j2].w);
                *(uint2*)(smc + OFF_A0 + (row * 136 + lane * 4) * 2) = u;
            }
        }
        __syncthreads();

        for (int j = jb; j < je; j++) {
            const uint32_t curA = ((j - jb) & 1) ? a1Addr : a0Addr;
            const char*   nxtP = smc + (((j - jb) & 1) ? OFF_A0 : OFF_A1);
            const bool hasnext = (j + 1 < je);
            const int spn = hasnext ? tile_sp(j + 1) : spc;

            // (1) issue ALL 16 LDGs for next tile (both batches, front-batched)
            int nidx = -1;
            float4 v0[8], v1[8];
            if (hasnext) {
                nidx = load_idx(j + 1, spn);
#pragma unroll
                for (int j2 = 0; j2 < 8; j2++) {
                    int idx = __shfl_sync(0xffffffffu, nidx, j2);
                    v0[j2] = make_float4(0.f, 0.f, 0.f, 0.f);
                    if (idx >= 0)
                        v0[j2] = *(const float4*)(desc + (size_t)idx * IN + lane * 4);
                }
#pragma unroll
                for (int j2 = 0; j2 < 8; j2++) {
                    int idx = __shfl_sync(0xffffffffu, nidx, 8 + j2);
                    v1[j2] = make_float4(0.f, 0.f, 0.f, 0.f);
                    if (idx >= 0)
                        v1[j2] = *(const float4*)(desc + (size_t)idx * IN + lane * 4);
                }
            }

            // (2) layer 0 MMA on current tile (16 loads in flight above)
            float d[4][4];
#pragma unroll
            for (int nt = 0; nt < 4; nt++)
#pragma unroll
                for (int i = 0; i < 4; i++) d[nt][i] = 0.f;
#pragma unroll
            for (int kk = 0; kk < 8; kk++) {
                const int k0 = kk * 16;
                uint32_t a0f, a1f, a2f, a3f;
                ldm4(a0f, a1f, a2f, a3f,
                     curA + ((wb + lrow) * 136 + k0 + lcol) * 2);
#pragma unroll
                for (int nt = 0; nt < 4; nt++) {
                    const __nv_bfloat16* bb = sW0 + (nt * 8 + gid) * 136 + k0 + 2 * tid;
                    uint32_t b0f = *(const uint32_t*)bb;
                    uint32_t b1f = *(const uint32_t*)(bb + 8);
                    mma16(d[nt][0], d[nt][1], d[nt][2], d[nt][3],
                          a0f, a1f, a2f, a3f, b0f, b1f);
                }
            }

            // (4) convert + store batch0 of next tile
            if (hasnext) {
#pragma unroll
                for (int j2 = 0; j2 < 8; j2++) {
                    int row = wb + j2;
                    uint2 u;
                    u.x = packbf2(v0[j2].x, v0[j2].y);
                    u.y = packbf2(v0[j2].z, v0[j2].w);
                    *(uint2*)(nxtP + (row * 136 + lane * 4) * 2) = u;
                }
            }

            // (5) epilogue0 + layer1 entirely in registers
            float e1[4][4];
#pragma unroll
            for (int nt = 0; nt < 4; nt++)
#pragma unroll
                for (int i = 0; i < 4; i++) e1[nt][i] = 0.f;
#pragma unroll
            for (int kk = 0; kk < 2; kk++) {
                const int cc0 = (2 * kk) * 8 + 2 * tid;
                const int cc1 = (2 * kk + 1) * 8 + 2 * tid;
                uint32_t a0f = packbf2(fast_tanh(d[2 * kk][0] + vb0[cc0]),
                                       fast_tanh(d[2 * kk][1] + vb0[cc0 + 1]));
                uint32_t a1f = packbf2(fast_tanh(d[2 * kk][2] + vb0[cc0]),
                                       fast_tanh(d[2 * kk][3] + vb0[cc0 + 1]));
                uint32_t a2f = packbf2(fast_tanh(d[2 * kk + 1][0] + vb0[cc1]),
                                       fast_tanh(d[2 * kk + 1][1] + vb0[cc1 + 1]));
                uint32_t a3f = packbf2(fast_tanh(d[2 * kk + 1][2] + vb0[cc1]),
                                       fast_tanh(d[2 * kk + 1][3] + vb0[cc1 + 1]));
                const int k0 = kk * 16;
#pragma unroll
                for (int nt = 0; nt < 4; nt++) {
                    const __nv_bfloat16* bb = sW1 + (nt * 8 + gid) * 40 + k0 + 2 * tid;
                    uint32_t b0f = *(const uint32_t*)bb;
                    uint32_t b1f = *(const uint32_t*)(bb + 8);
                    mma16(e1[nt][0], e1[nt][1], e1[nt][2], e1[nt][3],
                          a0f, a1f, a2f, a3f, b0f, b1f);
                }
            }

            // (6) epilogue 1: bias + tanh + W2 dot (energy)
            {
                float p0 = 0.f, p1e = 0.f;
#pragma unroll
                for (int nt = 0; nt < 4; nt++) {
                    int cc = nt * 8 + 2 * tid;
                    p0  += fast_tanh(e1[nt][0] + vb1[cc])     * vw2[cc];
                    p0  += fast_tanh(e1[nt][1] + vb1[cc + 1]) * vw2[cc + 1];
                    p1e += fast_tanh(e1[nt][2] + vb1[cc])     * vw2[cc];
                    p1e += fast_tanh(e1[nt][3] + vb1[cc + 1]) * vw2[cc + 1];
                }
                p0  += __shfl_xor_sync(0xffffffffu, p0, 1);
                p0  += __shfl_xor_sync(0xffffffffu, p0, 2);
                p1e += __shfl_xor_sync(0xffffffffu, p1e, 1);
                p1e += __shfl_xor_sync(0xffffffffu, p1e, 2);
                int i0 = __shfl_sync(0xffffffffu, cidx, gid);
                int i1 = __shfl_sync(0xffffffffu, cidx, gid + 8);
                if (tid == 0) {
                    float bb2 = vb2[0];
                    if (i0 >= 0) esum += p0 + bb2;
                    if (i1 >= 0) esum += p1e + bb2;
                }
            }

            // (7) convert + store batch1 of next tile
            if (hasnext) {
#pragma unroll
                for (int j2 = 0; j2 < 8; j2++) {
                    int row = wb + 8 + j2;
                    uint2 u;
                    u.x = packbf2(v1[j2].x, v1[j2].y);
                    u.y = packbf2(v1[j2].z, v1[j2].w);
                    *(uint2*)(nxtP + (row * 136 + lane * 4) * 2) = u;
                }
            }

            // (8) barrier: next buffer complete; cur free for reuse
            __syncthreads();

            // (9) species change -> reload weights (rare)
            if (hasnext && spn != spc) {
                load_weights(spn);
                __syncthreads();
            }
            spc = spn;
            cidx = nidx;
        }
    }

    // ---- block reduction of per-thread energy ----
    sred[t] = esum;
    __syncthreads();
    if (t < 128) sred[t] += sred[t + 128];
    __syncthreads();
    if (t < 64) sred[t] += sred[t + 64];
    __syncthreads();
    if (t < 32) {
        float v = sred[t] + sred[t + 32];
#pragma unroll
        for (int o = 16; o > 0; o >>= 1) v += __shfl_down_sync(0xffffffffu, v, o);
        if (t == 0) g_partial[blockIdx.x] = v;
    }

    // ---- last-block: final reduction + replay-state reset ----
    __shared__ int slast;
    __syncthreads();
    if (t == 0) {
        __threadfence();
        unsigned prev = atomicAdd(&g_done, 1u);
        slast = (prev + 1 == gridDim.x);
    }
    __syncthreads();
    if (slast) {
        float v = 0.f;
        for (int i = t; i < (int)gridDim.x; i += 256) v += g_partial[i];
        sred[t] = v;
        __syncthreads();
        if (t < 128) sred[t] += sred[t + 128];
        __syncthreads();
        if (t < 64) sred[t] += sred[t + 64];
        __syncthreads();
        if (t < 32) {
            float x = sred[t] + sred[t + 32];
#pragma unroll
            for (int o = 16; o > 0; o >>= 1) x += __shfl_down_sync(0xffffffffu, x, o);
            if (t == 0) out[0] = x;
        }
        if (t < NOS) g_cursor[t] = t * SEGA;
        if (t == 0) g_done = 0u;
    }
}

// ---------------- launcher: TWO kernels total ----------------
extern "C" void kernel_launch(void* const* d_in, const int* in_sizes, int n_in,
                              void* d_out, int out_size)
{
    const float* desc    = (const float*)d_in[0];
    const void*  species = d_in[1];
    const float* W0 = (const float*)d_in[2];
    const float* b0 = (const float*)d_in[3];
    const float* W1 = (const float*)d_in[4];
    const float* b1 = (const float*)d_in[5];
    const float* W2 = (const float*)d_in[6];
    const float* b2 = (const float*)d_in[7];

    int n = in_sizes[1];
    if (n > MAXN) n = MAXN;

    int nb_atoms = (n + 255) / 256;
    if (nb_atoms > MAXCB) nb_atoms = MAXCB;

    cudaFuncSetAttribute(k_mlp, cudaFuncAttributeMaxDynamicSharedMemorySize, SMEM_BYTES);

    k_scatter<<<nb_atoms, 256>>>(species, n);
    k_mlp<<<GRID_MLP, 256, SMEM_BYTES>>>(desc, W0, b0, W1, b1, W2, b2, (float*)d_out);
}